// round 14
// baseline (speedup 1.0000x reference)
#include <cuda_runtime.h>
#include <cuda_fp16.h>
#include <math.h>
#include <stdint.h>

// Shapes fixed by dataset: B=32, T=1024, J=1024, H=2048
#define BB 32
#define TT 1024
#define JJ 1024
#define HH 2048
#define MM (BB*TT)   // 32768

// ---------------- scratch ----------------
__device__ float  g_h [(size_t)MM * HH];
__device__ __half g_s16[(size_t)MM * HH];
__device__ __half g_x0[(size_t)MM * JJ];
__device__ __half g_x1[(size_t)MM * JJ];
__device__ __half g_w1a[(size_t)HH * JJ], g_w1b[(size_t)HH * JJ];
__device__ __half g_w2a[(size_t)HH * HH], g_w2b[(size_t)HH * HH];
__device__ __half g_w3a[(size_t)JJ * HH], g_w3b[(size_t)JJ * HH];
__device__ double g_sum1[HH], g_sq1[HH];
__device__ double g_sum2[HH], g_sq2[HH];
__device__ double g_sum3[JJ], g_sq3[JJ];

// ---------------- helpers ----------------
__device__ __forceinline__ void cpasync16(void* dst, const void* src) {
    unsigned sa = (unsigned)__cvta_generic_to_shared(dst);
    asm volatile("cp.async.cg.shared.global [%0], [%1], 16;\n" :: "r"(sa), "l"(src));
}
__device__ __forceinline__ void ldm4(uint32_t* r, const __half* p) {
    unsigned a = (unsigned)__cvta_generic_to_shared(p);
    asm volatile("ldmatrix.sync.aligned.m8n8.x4.shared.b16 {%0,%1,%2,%3}, [%4];"
                 : "=r"(r[0]), "=r"(r[1]), "=r"(r[2]), "=r"(r[3]) : "r"(a));
}
__device__ __forceinline__ void mma16816(float* c, const uint32_t* a, uint32_t b0, uint32_t b1) {
    asm volatile("mma.sync.aligned.m16n8k16.row.col.f32.f16.f16.f32 "
                 "{%0,%1,%2,%3},{%4,%5,%6,%7},{%8,%9},{%0,%1,%2,%3};"
                 : "+f"(c[0]), "+f"(c[1]), "+f"(c[2]), "+f"(c[3])
                 : "r"(a[0]), "r"(a[1]), "r"(a[2]), "r"(a[3]), "r"(b0), "r"(b1));
}

// ---------------- prep: vectorized split (4 elems/thread) + zero stat sums ----------------
__device__ __forceinline__ void split4(const float4 v, __half* a, __half* b, size_t i)
{
    __half h0 = __float2half_rn(v.x), h1 = __float2half_rn(v.y);
    __half h2 = __float2half_rn(v.z), h3 = __float2half_rn(v.w);
    __half2 hi01 = __halves2half2(h0, h1), hi23 = __halves2half2(h2, h3);
    __half2 lo01 = __halves2half2(__float2half_rn(v.x - __half2float(h0)),
                                  __float2half_rn(v.y - __half2float(h1)));
    __half2 lo23 = __halves2half2(__float2half_rn(v.z - __half2float(h2)),
                                  __float2half_rn(v.w - __half2float(h3)));
    *(__half2*)(a + i)     = hi01;
    *(__half2*)(a + i + 2) = hi23;
    *(__half2*)(b + i)     = lo01;
    *(__half2*)(b + i + 2) = lo23;
}

__global__ void prep_all(const float* __restrict__ x, const float* __restrict__ W1,
                         const float* __restrict__ W2, const float* __restrict__ W3)
{
    size_t t = (size_t)blockIdx.x * blockDim.x + threadIdx.x;
    if (t < HH) { g_sum1[t] = 0.0; g_sq1[t] = 0.0; g_sum2[t] = 0.0; g_sq2[t] = 0.0; }
    if (t < JJ) { g_sum3[t] = 0.0; g_sq3[t] = 0.0; }

    size_t i = t * 4;
    if (i < (size_t)MM * JJ)
        split4(*(const float4*)(x + i), g_x0, g_x1, i);
    if (i < (size_t)HH * JJ)
        split4(*(const float4*)(W1 + i), g_w1a, g_w1b, i);
    if (i < (size_t)HH * HH)
        split4(*(const float4*)(W2 + i), g_w2a, g_w2b, i);
    if (i < (size_t)JJ * HH)
        split4(*(const float4*)(W3 + i), g_w3a, g_w3b, i);
}

// ---------------- epilogue: store tile + fused column stats (warp tile 64x32) ----------------
__device__ __forceinline__ void epilogue_stats4(
    float acc[4][4][4], float* __restrict__ C, double* __restrict__ sum, double* __restrict__ sq,
    int N, int bm, int bn, int wm, int wn, int lane)
{
#pragma unroll
    for (int mt = 0; mt < 4; mt++) {
#pragma unroll
        for (int nt = 0; nt < 4; nt++) {
            int row = bm + wm * 64 + mt * 16 + (lane >> 2);
            int col = bn + wn * 32 + nt * 8 + (lane & 3) * 2;
            *(float2*)(C + (size_t)row * N + col)       = make_float2(acc[mt][nt][0], acc[mt][nt][1]);
            *(float2*)(C + (size_t)(row + 8) * N + col) = make_float2(acc[mt][nt][2], acc[mt][nt][3]);
        }
    }
#pragma unroll
    for (int nt = 0; nt < 4; nt++) {
        float s0 = 0.f, q0 = 0.f, s1 = 0.f, q1 = 0.f;
#pragma unroll
        for (int mt = 0; mt < 4; mt++) {
            float a0 = acc[mt][nt][0], a1 = acc[mt][nt][1];
            float a2 = acc[mt][nt][2], a3 = acc[mt][nt][3];
            s0 += a0 + a2;  q0 += a0 * a0 + a2 * a2;
            s1 += a1 + a3;  q1 += a1 * a1 + a3 * a3;
        }
#pragma unroll
        for (int off = 16; off >= 4; off >>= 1) {
            s0 += __shfl_down_sync(0xffffffffu, s0, off);
            q0 += __shfl_down_sync(0xffffffffu, q0, off);
            s1 += __shfl_down_sync(0xffffffffu, s1, off);
            q1 += __shfl_down_sync(0xffffffffu, q1, off);
        }
        if (lane < 4) {
            int col = bn + wn * 32 + nt * 8 + lane * 2;
            atomicAdd(&sum[col],     (double)s0);
            atomicAdd(&sq[col],      (double)q0);
            atomicAdd(&sum[col + 1], (double)s1);
            atomicAdd(&sq[col + 1],  (double)q1);
        }
    }
}

// ---------------- GEMM tiles ----------------
// k32 arrays (layer 1)
#define TSH 40
#define ARRH (128*TSH)
#define ARRB (ARRH*2)
// k64 arrays (layers 2/3)
#define TS2 72
#define ARR2H (128*TS2)
#define ARR2B (ARR2H*2)

// ======= layer-1 fused: 8 warps, warp tile 64x32, k32, 2-stage, spread loads =======
__global__ __launch_bounds__(256, 2) void gemm_l1(
    const __half* __restrict__ A0g, const __half* __restrict__ A1g,
    const __half* __restrict__ B0g, const __half* __restrict__ B1g,
    float* __restrict__ C, double* __restrict__ sum, double* __restrict__ sq,
    int N, int K)
{
    extern __shared__ __half smem[];
    constexpr uint32_t STAGEB = 4 * ARRB;

    const int tid  = threadIdx.x;
    const int lane = tid & 31;
    const int warp = tid >> 5;
    const int wm   = warp >> 2;
    const int wn   = warp & 3;
    const int bm   = blockIdx.y * 128;
    const int bn   = blockIdx.x * 128;

    const __half* gbase[4];
    gbase[0] = A0g + (size_t)bm * K;
    gbase[1] = A1g + (size_t)bm * K;
    gbase[2] = B0g + (size_t)bn * K;
    gbase[3] = B1g + (size_t)bn * K;

    float acc[4][4][4];
#pragma unroll
    for (int i = 0; i < 4; i++)
#pragma unroll
        for (int j = 0; j < 4; j++)
#pragma unroll
            for (int k = 0; k < 4; k++) acc[i][j][k] = 0.0f;

    const int NK = K >> 5;

    // load chunk: arrays [a0,a1) of stage
    auto load_chunk = [&](int kt, int slot, int a0c, int a1c) {
        const int kb = kt << 5;
        char* sb = (char*)smem + (uint32_t)slot * STAGEB;
#pragma unroll
        for (int a = 0; a < 4; a++) {
            if (a < a0c || a >= a1c) continue;
            const __half* g = gbase[a];
            char* sa = sb + a * ARRB;
#pragma unroll
            for (int c = tid; c < 512; c += 256) {
                int r = c >> 2, q = c & 3;
                cpasync16(sa + r * (TSH*2) + q * 16, g + (size_t)r * K + kb + q * 8);
            }
        }
    };

    load_chunk(0, 0, 0, 4);
    asm volatile("cp.async.commit_group;");

    for (int kt = 0; kt < NK; kt++) {
        asm volatile("cp.async.wait_group 0;");
        __syncthreads();

        const bool ld = (kt + 1 < NK);
        const int nslot = (kt + 1) & 1;

        const __half* sb = smem + (uint32_t)((kt & 1) * STAGEB / 2);
        const __half* tA0 = sb;
        const __half* tA1 = sb + ARRH;
        const __half* tB0 = sb + 2 * ARRH;
        const __half* tB1 = sb + 3 * ARRH;

#pragma unroll
        for (int k16 = 0; k16 < 32; k16 += 16) {
            const int ra = wm * 64 + (lane & 7) + ((lane >> 3) & 1) * 8;
            const int ka = k16 + (lane >> 4) * 8;
            const int rb = wn * 32 + (lane & 7) + (lane >> 4) * 8;
            const int kb2 = k16 + ((lane >> 3) & 1) * 8;

            uint32_t a0[4][4], a1[4][4], b0[2][4], b1[2][4];
#pragma unroll
            for (int mt = 0; mt < 4; mt++) ldm4(a0[mt], tA0 + (ra + mt * 16) * TSH + ka);
#pragma unroll
            for (int g = 0; g < 2; g++)  ldm4(b0[g], tB0 + (rb + g * 16) * TSH + kb2);
#pragma unroll
            for (int mt = 0; mt < 4; mt++)
#pragma unroll
                for (int nt = 0; nt < 4; nt++)
                    mma16816(acc[mt][nt], a0[mt], b0[nt >> 1][(nt & 1) * 2], b0[nt >> 1][(nt & 1) * 2 + 1]);

            // spread next-stage loads between MMA blocks
            if (ld) load_chunk(kt + 1, nslot, (k16 == 0) ? 0 : 2, (k16 == 0) ? 2 : 4);

#pragma unroll
            for (int mt = 0; mt < 4; mt++) ldm4(a1[mt], tA1 + (ra + mt * 16) * TSH + ka);
#pragma unroll
            for (int mt = 0; mt < 4; mt++)
#pragma unroll
                for (int nt = 0; nt < 4; nt++)
                    mma16816(acc[mt][nt], a1[mt], b0[nt >> 1][(nt & 1) * 2], b0[nt >> 1][(nt & 1) * 2 + 1]);

#pragma unroll
            for (int g = 0; g < 2; g++)  ldm4(b1[g], tB1 + (rb + g * 16) * TSH + kb2);
#pragma unroll
            for (int mt = 0; mt < 4; mt++)
#pragma unroll
                for (int nt = 0; nt < 4; nt++)
                    mma16816(acc[mt][nt], a0[mt], b1[nt >> 1][(nt & 1) * 2], b1[nt >> 1][(nt & 1) * 2 + 1]);
        }
        if (ld) asm volatile("cp.async.commit_group;");
        __syncthreads();
    }

    epilogue_stats4(acc, C, sum, sq, N, bm, bn, wm, wn, lane);
}

// ======= layers 2/3: 8 warps, warp tile 64x32, k64 tiles, 2-stage, spread loads =======
__global__ __launch_bounds__(256, 2) void gemm_v2(
    const __half* __restrict__ A, const __half* __restrict__ B0, const __half* __restrict__ B1,
    float* __restrict__ C, double* __restrict__ sum, double* __restrict__ sq,
    int N, int K)
{
    constexpr uint32_t STAGEB = 3 * ARR2B;     // 55296 B
    extern __shared__ __half smem[];

    const int tid  = threadIdx.x;
    const int lane = tid & 31;
    const int warp = tid >> 5;
    const int wm   = warp >> 2;
    const int wn   = warp & 3;
    const int bm   = blockIdx.y * 128;
    const int bn   = blockIdx.x * 128;

    const __half* gbase[3];
    gbase[0] = A  + (size_t)bm * K;
    gbase[1] = B0 + (size_t)bn * K;
    gbase[2] = B1 + (size_t)bn * K;

    float acc[4][4][4];
#pragma unroll
    for (int i = 0; i < 4; i++)
#pragma unroll
        for (int j = 0; j < 4; j++)
#pragma unroll
            for (int k = 0; k < 4; k++) acc[i][j][k] = 0.0f;

    const int NK = K >> 6;   // k64 tiles

    // load chunk: array index a only
    auto load_chunk = [&](int kt, int slot, int a) {
        const int kb = kt << 6;
        char* sb = (char*)smem + (uint32_t)slot * STAGEB;
        const __half* g = gbase[a];
        char* sa = sb + a * ARR2B;
#pragma unroll
        for (int c = tid; c < 1024; c += 256) {
            int r = c >> 3, q = c & 7;
            cpasync16(sa + r * (TS2*2) + q * 16, g + (size_t)r * K + kb + q * 8);
        }
    };

    load_chunk(0, 0, 0); load_chunk(0, 0, 1); load_chunk(0, 0, 2);
    asm volatile("cp.async.commit_group;");

    for (int kt = 0; kt < NK; kt++) {
        asm volatile("cp.async.wait_group 0;");
        __syncthreads();

        const bool ld = (kt + 1 < NK);
        const int nslot = (kt + 1) & 1;

        const __half* sb = smem + (uint32_t)((kt & 1) * STAGEB / 2);
        const __half* tA  = sb;
        const __half* tB0 = sb + ARR2H;
        const __half* tB1 = sb + 2 * ARR2H;

#pragma unroll
        for (int k16 = 0; k16 < 64; k16 += 16) {
            uint32_t af[4][4];
            {
                int r  = wm * 64 + (lane & 7) + ((lane >> 3) & 1) * 8;
                int kc = k16 + (lane >> 4) * 8;
#pragma unroll
                for (int mt = 0; mt < 4; mt++)
                    ldm4(af[mt], tA + (r + mt * 16) * TS2 + kc);
            }
#pragma unroll
            for (int p = 0; p < 2; p++) {
                const __half* tB = p ? tB1 : tB0;
                uint32_t bf[2][4];
                {
                    int r  = wn * 32 + (lane & 7) + (lane >> 4) * 8;
                    int kc = k16 + ((lane >> 3) & 1) * 8;
#pragma unroll
                    for (int g = 0; g < 2; g++)
                        ldm4(bf[g], tB + (r + g * 16) * TS2 + kc);
                }
#pragma unroll
                for (int mt = 0; mt < 4; mt++)
#pragma unroll
                    for (int nt = 0; nt < 4; nt++)
                        mma16816(acc[mt][nt], af[mt],
                                 bf[nt >> 1][(nt & 1) * 2], bf[nt >> 1][(nt & 1) * 2 + 1]);
            }
            // spread next-stage loads: one array after each of the first 3 blocks
            if (ld && k16 < 48) load_chunk(kt + 1, nslot, k16 >> 4);
        }
        if (ld) asm volatile("cp.async.commit_group;");
        __syncthreads();
    }

    epilogue_stats4(acc, C, sum, sq, N, bm, bn, wm, wn, lane);
}

// ---------------- BatchNorm + LIF scan (2 channels per thread) ----------------
template <typename OutT>
__global__ void lif_scan2(const float* __restrict__ h,
                          const double* __restrict__ sum, const double* __restrict__ sq,
                          const float* __restrict__ gamma, const float* __restrict__ bias,
                          const float* __restrict__ betap, const float* __restrict__ U0,
                          OutT* __restrict__ S, int Bn, int T, int I)
{
    int idx = blockIdx.x * blockDim.x + threadIdx.x;   // (b * I/2 + i2)
    if (idx >= Bn * (I >> 1)) return;
    int b = idx / (I >> 1);
    int i = (idx - b * (I >> 1)) * 2;

    const double inv = 1.0 / (double)(Bn * T);
    float m0, m1, r0, r1;
    {
        double mu0 = sum[i] * inv,     mu1 = sum[i + 1] * inv;
        double v0 = sq[i] * inv - mu0 * mu0, v1 = sq[i + 1] * inv - mu1 * mu1;
        m0 = (float)mu0; m1 = (float)mu1;
        r0 = (float)(1.0 / sqrt(v0 + 1e-5));
        r1 = (float)(1.0 / sqrt(v1 + 1e-5));
    }
    float g0 = gamma[i], g1 = gamma[i + 1];
    float b0 = bias[i],  b1 = bias[i + 1];
    float be0 = (float)(1.0 / (1.0 + exp(-(double)betap[i])));
    float be1 = (float)(1.0 / (1.0 + exp(-(double)betap[i + 1])));
    float ob0 = 1.0f - be0, ob1 = 1.0f - be1;

    const float2* u0p = (const float2*)(U0 + (size_t)b * I + i);
    float2 Uv = *u0p;
    float U0v = Uv.x, U1v = Uv.y;
    float S0 = 0.0f, S1 = 0.0f;

    const float2* hp = (const float2*)(h + (size_t)b * T * I + i);
    OutT* sp = S + (size_t)b * T * I + i;
    const int strideV = I >> 1;

    for (int t = 0; t < T; t++) {
        float2 hv = hp[(size_t)t * strideV];
        float x0 = ((hv.x - m0) * r0) * g0 + b0;
        float x1 = ((hv.y - m1) * r1) * g1 + b1;
        U0v = be0 * (U0v - S0) + ob0 * x0;
        U1v = be1 * (U1v - S1) + ob1 * x1;
        S0 = (U0v >= 1.0f) ? 1.0f : 0.0f;
        S1 = (U1v >= 1.0f) ? 1.0f : 0.0f;
        sp[(size_t)t * I]     = (OutT)S0;
        sp[(size_t)t * I + 1] = (OutT)S1;
    }
}

// ---------------- driver ----------------
extern "C" void kernel_launch(void* const* d_in, const int* in_sizes, int n_in,
                              void* d_out, int out_size)
{
    const float* x      = (const float*)d_in[0];
    const float* W1     = (const float*)d_in[1];
    const float* beta1  = (const float*)d_in[2];
    const float* gamma1 = (const float*)d_in[3];
    const float* bias1  = (const float*)d_in[4];
    const float* U01    = (const float*)d_in[5];
    const float* W2     = (const float*)d_in[6];
    const float* beta2  = (const float*)d_in[7];
    const float* gamma2 = (const float*)d_in[8];
    const float* bias2  = (const float*)d_in[9];
    const float* U02    = (const float*)d_in[10];
    const float* W3     = (const float*)d_in[11];
    const float* beta3  = (const float*)d_in[12];
    const float* gamma3 = (const float*)d_in[13];
    const float* bias3  = (const float*)d_in[14];
    const float* U03    = (const float*)d_in[15];
    float* out = (float*)d_out;

    float *h; __half *s16, *x0, *x1, *w1a, *w1b, *w2a, *w2b, *w3a, *w3b;
    double *sum1, *sq1, *sum2, *sq2, *sum3, *sq3;
    cudaGetSymbolAddress((void**)&h,   g_h);
    cudaGetSymbolAddress((void**)&s16, g_s16);
    cudaGetSymbolAddress((void**)&x0,  g_x0);
    cudaGetSymbolAddress((void**)&x1,  g_x1);
    cudaGetSymbolAddress((void**)&w1a, g_w1a);
    cudaGetSymbolAddress((void**)&w1b, g_w1b);
    cudaGetSymbolAddress((void**)&w2a, g_w2a);
    cudaGetSymbolAddress((void**)&w2b, g_w2b);
    cudaGetSymbolAddress((void**)&w3a, g_w3a);
    cudaGetSymbolAddress((void**)&w3b, g_w3b);
    cudaGetSymbolAddress((void**)&sum1, g_sum1);
    cudaGetSymbolAddress((void**)&sq1,  g_sq1);
    cudaGetSymbolAddress((void**)&sum2, g_sum2);
    cudaGetSymbolAddress((void**)&sq2,  g_sq2);
    cudaGetSymbolAddress((void**)&sum3, g_sum3);
    cudaGetSymbolAddress((void**)&sq3,  g_sq3);

    const int SML1 = 2 * 4 * ARRB;    // 81920 B
    const int SMV2 = 2 * 3 * ARR2B;   // 110592 B
    cudaFuncSetAttribute(gemm_l1, cudaFuncAttributeMaxDynamicSharedMemorySize, SML1);
    cudaFuncSetAttribute(gemm_v2, cudaFuncAttributeMaxDynamicSharedMemorySize, SMV2);

    // 0: prep (vectorized, 4 elems/thread)
    prep_all<<<(unsigned)(((size_t)MM * JJ / 4 + 255) / 256), 256>>>(x, W1, W2, W3);

    // 1: layer-1 fused GEMM (+stats)
    gemm_l1<<<dim3(HH / 128, MM / 128), 256, SML1>>>(x0, x1, w1a, w1b, h, sum1, sq1, HH, JJ);
    // 2: lif 1
    lif_scan2<__half><<<(BB * HH / 2 + 255) / 256, 256>>>(h, sum1, sq1, gamma1, bias1, beta1, U01, s16, BB, TT, HH);

    // 3: layer-2 GEMM (+stats)  <-- ncu captures this
    gemm_v2<<<dim3(HH / 128, MM / 128), 256, SMV2>>>(s16, w2a, w2b, h, sum2, sq2, HH, HH);
    // 4: lif 2
    lif_scan2<__half><<<(BB * HH / 2 + 255) / 256, 256>>>(h, sum2, sq2, gamma2, bias2, beta2, U02, s16, BB, TT, HH);

    // 5: layer-3 GEMM (+stats)
    gemm_v2<<<dim3(JJ / 128, MM / 128), 256, SMV2>>>(s16, w3a, w3b, h, sum3, sq3, JJ, HH);
    // 6: lif 3
    lif_scan2<float><<<(BB * JJ / 2 + 255) / 256, 256>>>(h, sum3, sq3, gamma3, bias3, beta3, U03, out, BB, TT, JJ);
}

// round 16
// speedup vs baseline: 1.1889x; 1.1889x over previous
#include <cuda_runtime.h>
#include <cuda_fp16.h>
#include <math.h>
#include <stdint.h>

// Shapes fixed by dataset: B=32, T=1024, J=1024, H=2048
#define BB 32
#define TT 1024
#define JJ 1024
#define HH 2048
#define MM (BB*TT)   // 32768

// ---------------- scratch ----------------
__device__ float  g_h [(size_t)MM * HH];
__device__ __half g_s16[(size_t)MM * HH];
__device__ __half g_x0[(size_t)MM * JJ];
__device__ __half g_x1[(size_t)MM * JJ];
__device__ __half g_w1a[(size_t)HH * JJ], g_w1b[(size_t)HH * JJ];
__device__ __half g_w2a[(size_t)HH * HH], g_w2b[(size_t)HH * HH];
__device__ __half g_w3a[(size_t)JJ * HH], g_w3b[(size_t)JJ * HH];
__device__ double g_sum1[HH], g_sq1[HH];
__device__ double g_sum2[HH], g_sq2[HH];
__device__ double g_sum3[JJ], g_sq3[JJ];

// ---------------- helpers ----------------
__device__ __forceinline__ void cpasync16(void* dst, const void* src) {
    unsigned sa = (unsigned)__cvta_generic_to_shared(dst);
    asm volatile("cp.async.cg.shared.global [%0], [%1], 16;\n" :: "r"(sa), "l"(src));
}
__device__ __forceinline__ void ldm4(uint32_t* r, const __half* p) {
    unsigned a = (unsigned)__cvta_generic_to_shared(p);
    asm volatile("ldmatrix.sync.aligned.m8n8.x4.shared.b16 {%0,%1,%2,%3}, [%4];"
                 : "=r"(r[0]), "=r"(r[1]), "=r"(r[2]), "=r"(r[3]) : "r"(a));
}
__device__ __forceinline__ void mma16816(float* c, const uint32_t* a, uint32_t b0, uint32_t b1) {
    asm volatile("mma.sync.aligned.m16n8k16.row.col.f32.f16.f16.f32 "
                 "{%0,%1,%2,%3},{%4,%5,%6,%7},{%8,%9},{%0,%1,%2,%3};"
                 : "+f"(c[0]), "+f"(c[1]), "+f"(c[2]), "+f"(c[3])
                 : "r"(a[0]), "r"(a[1]), "r"(a[2]), "r"(a[3]), "r"(b0), "r"(b1));
}

// ---------------- prep: vectorized split (4 elems/thread) + zero stat sums ----------------
__device__ __forceinline__ void split4(const float4 v, __half* a, __half* b, size_t i)
{
    __half h0 = __float2half_rn(v.x), h1 = __float2half_rn(v.y);
    __half h2 = __float2half_rn(v.z), h3 = __float2half_rn(v.w);
    __half2 hi01 = __halves2half2(h0, h1), hi23 = __halves2half2(h2, h3);
    __half2 lo01 = __halves2half2(__float2half_rn(v.x - __half2float(h0)),
                                  __float2half_rn(v.y - __half2float(h1)));
    __half2 lo23 = __halves2half2(__float2half_rn(v.z - __half2float(h2)),
                                  __float2half_rn(v.w - __half2float(h3)));
    *(__half2*)(a + i)     = hi01;
    *(__half2*)(a + i + 2) = hi23;
    *(__half2*)(b + i)     = lo01;
    *(__half2*)(b + i + 2) = lo23;
}

__global__ void prep_all(const float* __restrict__ x, const float* __restrict__ W1,
                         const float* __restrict__ W2, const float* __restrict__ W3)
{
    size_t t = (size_t)blockIdx.x * blockDim.x + threadIdx.x;
    if (t < HH) { g_sum1[t] = 0.0; g_sq1[t] = 0.0; g_sum2[t] = 0.0; g_sq2[t] = 0.0; }
    if (t < JJ) { g_sum3[t] = 0.0; g_sq3[t] = 0.0; }

    size_t i = t * 4;
    if (i < (size_t)MM * JJ)
        split4(*(const float4*)(x + i), g_x0, g_x1, i);
    if (i < (size_t)HH * JJ)
        split4(*(const float4*)(W1 + i), g_w1a, g_w1b, i);
    if (i < (size_t)HH * HH)
        split4(*(const float4*)(W2 + i), g_w2a, g_w2b, i);
    if (i < (size_t)JJ * HH)
        split4(*(const float4*)(W3 + i), g_w3a, g_w3b, i);
}

// ---------------- epilogue: store tile + fused column stats (warp tile 64x32) ----------------
__device__ __forceinline__ void epilogue_stats4(
    float acc[4][4][4], float* __restrict__ C, double* __restrict__ sum, double* __restrict__ sq,
    int N, int bm, int bn, int wm, int wn, int lane)
{
#pragma unroll
    for (int mt = 0; mt < 4; mt++) {
#pragma unroll
        for (int nt = 0; nt < 4; nt++) {
            int row = bm + wm * 64 + mt * 16 + (lane >> 2);
            int col = bn + wn * 32 + nt * 8 + (lane & 3) * 2;
            *(float2*)(C + (size_t)row * N + col)       = make_float2(acc[mt][nt][0], acc[mt][nt][1]);
            *(float2*)(C + (size_t)(row + 8) * N + col) = make_float2(acc[mt][nt][2], acc[mt][nt][3]);
        }
    }
#pragma unroll
    for (int nt = 0; nt < 4; nt++) {
        float s0 = 0.f, q0 = 0.f, s1 = 0.f, q1 = 0.f;
#pragma unroll
        for (int mt = 0; mt < 4; mt++) {
            float a0 = acc[mt][nt][0], a1 = acc[mt][nt][1];
            float a2 = acc[mt][nt][2], a3 = acc[mt][nt][3];
            s0 += a0 + a2;  q0 += a0 * a0 + a2 * a2;
            s1 += a1 + a3;  q1 += a1 * a1 + a3 * a3;
        }
#pragma unroll
        for (int off = 16; off >= 4; off >>= 1) {
            s0 += __shfl_down_sync(0xffffffffu, s0, off);
            q0 += __shfl_down_sync(0xffffffffu, q0, off);
            s1 += __shfl_down_sync(0xffffffffu, s1, off);
            q1 += __shfl_down_sync(0xffffffffu, q1, off);
        }
        if (lane < 4) {
            int col = bn + wn * 32 + nt * 8 + lane * 2;
            atomicAdd(&sum[col],     (double)s0);
            atomicAdd(&sq[col],      (double)q0);
            atomicAdd(&sum[col + 1], (double)s1);
            atomicAdd(&sq[col + 1],  (double)q1);
        }
    }
}

// ---------------- GEMM tiles ----------------
// k32 arrays (layer 1)
#define TSH 40
#define ARRH (128*TSH)
#define ARRB (ARRH*2)
// k64 arrays (layers 2/3)
#define TS2 72
#define ARR2H (128*TS2)
#define ARR2B (ARR2H*2)

// ======= layer-1 fused: 8 warps, warp tile 64x32, k32, 2-stage, spread loads =======
__global__ __launch_bounds__(256, 2) void gemm_l1(
    const __half* __restrict__ A0g, const __half* __restrict__ A1g,
    const __half* __restrict__ B0g, const __half* __restrict__ B1g,
    float* __restrict__ C, double* __restrict__ sum, double* __restrict__ sq,
    int N, int K)
{
    extern __shared__ __half smem[];
    constexpr uint32_t STAGEB = 4 * ARRB;

    const int tid  = threadIdx.x;
    const int lane = tid & 31;
    const int warp = tid >> 5;
    const int wm   = warp >> 2;
    const int wn   = warp & 3;
    const int bm   = blockIdx.y * 128;
    const int bn   = blockIdx.x * 128;

    const __half* gbase[4];
    gbase[0] = A0g + (size_t)bm * K;
    gbase[1] = A1g + (size_t)bm * K;
    gbase[2] = B0g + (size_t)bn * K;
    gbase[3] = B1g + (size_t)bn * K;

    float acc[4][4][4];
#pragma unroll
    for (int i = 0; i < 4; i++)
#pragma unroll
        for (int j = 0; j < 4; j++)
#pragma unroll
            for (int k = 0; k < 4; k++) acc[i][j][k] = 0.0f;

    const int NK = K >> 5;

    auto load_chunk = [&](int kt, int slot, int a0c, int a1c) {
        const int kb = kt << 5;
        char* sb = (char*)smem + (uint32_t)slot * STAGEB;
#pragma unroll
        for (int a = 0; a < 4; a++) {
            if (a < a0c || a >= a1c) continue;
            const __half* g = gbase[a];
            char* sa = sb + a * ARRB;
#pragma unroll
            for (int c = tid; c < 512; c += 256) {
                int r = c >> 2, q = c & 3;
                cpasync16(sa + r * (TSH*2) + q * 16, g + (size_t)r * K + kb + q * 8);
            }
        }
    };

    load_chunk(0, 0, 0, 4);
    asm volatile("cp.async.commit_group;");

    for (int kt = 0; kt < NK; kt++) {
        asm volatile("cp.async.wait_group 0;");
        __syncthreads();

        const bool ld = (kt + 1 < NK);
        const int nslot = (kt + 1) & 1;

        const __half* sb = smem + (uint32_t)((kt & 1) * STAGEB / 2);
        const __half* tA0 = sb;
        const __half* tA1 = sb + ARRH;
        const __half* tB0 = sb + 2 * ARRH;
        const __half* tB1 = sb + 3 * ARRH;

#pragma unroll
        for (int k16 = 0; k16 < 32; k16 += 16) {
            const int ra = wm * 64 + (lane & 7) + ((lane >> 3) & 1) * 8;
            const int ka = k16 + (lane >> 4) * 8;
            const int rb = wn * 32 + (lane & 7) + (lane >> 4) * 8;
            const int kb2 = k16 + ((lane >> 3) & 1) * 8;

            uint32_t a0[4][4], a1[4][4], b0[2][4], b1[2][4];
#pragma unroll
            for (int mt = 0; mt < 4; mt++) ldm4(a0[mt], tA0 + (ra + mt * 16) * TSH + ka);
#pragma unroll
            for (int g = 0; g < 2; g++)  ldm4(b0[g], tB0 + (rb + g * 16) * TSH + kb2);
#pragma unroll
            for (int mt = 0; mt < 4; mt++)
#pragma unroll
                for (int nt = 0; nt < 4; nt++)
                    mma16816(acc[mt][nt], a0[mt], b0[nt >> 1][(nt & 1) * 2], b0[nt >> 1][(nt & 1) * 2 + 1]);

            if (ld) load_chunk(kt + 1, nslot, (k16 == 0) ? 0 : 2, (k16 == 0) ? 2 : 4);

#pragma unroll
            for (int mt = 0; mt < 4; mt++) ldm4(a1[mt], tA1 + (ra + mt * 16) * TSH + ka);
#pragma unroll
            for (int mt = 0; mt < 4; mt++)
#pragma unroll
                for (int nt = 0; nt < 4; nt++)
                    mma16816(acc[mt][nt], a1[mt], b0[nt >> 1][(nt & 1) * 2], b0[nt >> 1][(nt & 1) * 2 + 1]);

#pragma unroll
            for (int g = 0; g < 2; g++)  ldm4(b1[g], tB1 + (rb + g * 16) * TSH + kb2);
#pragma unroll
            for (int mt = 0; mt < 4; mt++)
#pragma unroll
                for (int nt = 0; nt < 4; nt++)
                    mma16816(acc[mt][nt], a0[mt], b1[nt >> 1][(nt & 1) * 2], b1[nt >> 1][(nt & 1) * 2 + 1]);
        }
        if (ld) asm volatile("cp.async.commit_group;");
        __syncthreads();
    }

    epilogue_stats4(acc, C, sum, sq, N, bm, bn, wm, wn, lane);
}

// ======= layers 2/3: 8 warps, warp tile 64x32, k64 tiles, 2-stage, spread loads =======
__global__ __launch_bounds__(256, 2) void gemm_v2(
    const __half* __restrict__ A, const __half* __restrict__ B0, const __half* __restrict__ B1,
    float* __restrict__ C, double* __restrict__ sum, double* __restrict__ sq,
    int N, int K)
{
    constexpr uint32_t STAGEB = 3 * ARR2B;     // 55296 B
    extern __shared__ __half smem[];

    const int tid  = threadIdx.x;
    const int lane = tid & 31;
    const int warp = tid >> 5;
    const int wm   = warp >> 2;
    const int wn   = warp & 3;
    const int bm   = blockIdx.y * 128;
    const int bn   = blockIdx.x * 128;

    const __half* gbase[3];
    gbase[0] = A  + (size_t)bm * K;
    gbase[1] = B0 + (size_t)bn * K;
    gbase[2] = B1 + (size_t)bn * K;

    float acc[4][4][4];
#pragma unroll
    for (int i = 0; i < 4; i++)
#pragma unroll
        for (int j = 0; j < 4; j++)
#pragma unroll
            for (int k = 0; k < 4; k++) acc[i][j][k] = 0.0f;

    const int NK = K >> 6;   // k64 tiles

    auto load_chunk = [&](int kt, int slot, int a) {
        const int kb = kt << 6;
        char* sb = (char*)smem + (uint32_t)slot * STAGEB;
        const __half* g = gbase[a];
        char* sa = sb + a * ARR2B;
#pragma unroll
        for (int c = tid; c < 1024; c += 256) {
            int r = c >> 3, q = c & 7;
            cpasync16(sa + r * (TS2*2) + q * 16, g + (size_t)r * K + kb + q * 8);
        }
    };

    load_chunk(0, 0, 0); load_chunk(0, 0, 1); load_chunk(0, 0, 2);
    asm volatile("cp.async.commit_group;");

    for (int kt = 0; kt < NK; kt++) {
        asm volatile("cp.async.wait_group 0;");
        __syncthreads();

        const bool ld = (kt + 1 < NK);
        const int nslot = (kt + 1) & 1;

        const __half* sb = smem + (uint32_t)((kt & 1) * STAGEB / 2);
        const __half* tA  = sb;
        const __half* tB0 = sb + ARR2H;
        const __half* tB1 = sb + 2 * ARR2H;

#pragma unroll
        for (int k16 = 0; k16 < 64; k16 += 16) {
            uint32_t af[4][4];
            {
                int r  = wm * 64 + (lane & 7) + ((lane >> 3) & 1) * 8;
                int kc = k16 + (lane >> 4) * 8;
#pragma unroll
                for (int mt = 0; mt < 4; mt++)
                    ldm4(af[mt], tA + (r + mt * 16) * TS2 + kc);
            }
#pragma unroll
            for (int p = 0; p < 2; p++) {
                const __half* tB = p ? tB1 : tB0;
                uint32_t bf[2][4];
                {
                    int r  = wn * 32 + (lane & 7) + (lane >> 4) * 8;
                    int kc = k16 + ((lane >> 3) & 1) * 8;
#pragma unroll
                    for (int g = 0; g < 2; g++)
                        ldm4(bf[g], tB + (r + g * 16) * TS2 + kc);
                }
#pragma unroll
                for (int mt = 0; mt < 4; mt++)
#pragma unroll
                    for (int nt = 0; nt < 4; nt++)
                        mma16816(acc[mt][nt], af[mt],
                                 bf[nt >> 1][(nt & 1) * 2], bf[nt >> 1][(nt & 1) * 2 + 1]);
            }
            if (ld && k16 < 48) load_chunk(kt + 1, nslot, k16 >> 4);
        }
        if (ld) asm volatile("cp.async.commit_group;");
        __syncthreads();
    }

    epilogue_stats4(acc, C, sum, sq, N, bm, bn, wm, wn, lane);
}

// ---------------- BatchNorm + LIF scan (scalar, 1 channel/thread — R13 proven) ----------------
template <typename OutT>
__global__ void lif_scan(const float* __restrict__ h,
                         const double* __restrict__ sum, const double* __restrict__ sq,
                         const float* __restrict__ gamma, const float* __restrict__ bias,
                         const float* __restrict__ betap, const float* __restrict__ U0,
                         OutT* __restrict__ S, int Bn, int T, int I)
{
    int idx = blockIdx.x * blockDim.x + threadIdx.x;
    if (idx >= Bn * I) return;
    int b = idx / I, i = idx - b * I;

    const double inv = 1.0 / (double)(Bn * T);
    double mu_d = sum[i] * inv;
    double var_d = sq[i] * inv - mu_d * mu_d;
    float m = (float)mu_d;
    float rstd = (float)(1.0 / sqrt(var_d + 1e-5));
    float g = gamma[i], bi = bias[i];
    float beta = (float)(1.0 / (1.0 + exp(-(double)betap[i])));
    float ombeta = 1.0f - beta;

    float U = U0[idx], Sv = 0.0f;
    const float* hp = h + (size_t)b * T * I + i;
    OutT* sp = S + (size_t)b * T * I + i;

    for (int t = 0; t < T; t++) {
        float x = ((hp[(size_t)t * I] - m) * rstd) * g + bi;
        U = beta * (U - Sv) + ombeta * x;
        Sv = (U >= 1.0f) ? 1.0f : 0.0f;
        sp[(size_t)t * I] = (OutT)Sv;
    }
}

// ---------------- driver ----------------
extern "C" void kernel_launch(void* const* d_in, const int* in_sizes, int n_in,
                              void* d_out, int out_size)
{
    const float* x      = (const float*)d_in[0];
    const float* W1     = (const float*)d_in[1];
    const float* beta1  = (const float*)d_in[2];
    const float* gamma1 = (const float*)d_in[3];
    const float* bias1  = (const float*)d_in[4];
    const float* U01    = (const float*)d_in[5];
    const float* W2     = (const float*)d_in[6];
    const float* beta2  = (const float*)d_in[7];
    const float* gamma2 = (const float*)d_in[8];
    const float* bias2  = (const float*)d_in[9];
    const float* U02    = (const float*)d_in[10];
    const float* W3     = (const float*)d_in[11];
    const float* beta3  = (const float*)d_in[12];
    const float* gamma3 = (const float*)d_in[13];
    const float* bias3  = (const float*)d_in[14];
    const float* U03    = (const float*)d_in[15];
    float* out = (float*)d_out;

    float *h; __half *s16, *x0, *x1, *w1a, *w1b, *w2a, *w2b, *w3a, *w3b;
    double *sum1, *sq1, *sum2, *sq2, *sum3, *sq3;
    cudaGetSymbolAddress((void**)&h,   g_h);
    cudaGetSymbolAddress((void**)&s16, g_s16);
    cudaGetSymbolAddress((void**)&x0,  g_x0);
    cudaGetSymbolAddress((void**)&x1,  g_x1);
    cudaGetSymbolAddress((void**)&w1a, g_w1a);
    cudaGetSymbolAddress((void**)&w1b, g_w1b);
    cudaGetSymbolAddress((void**)&w2a, g_w2a);
    cudaGetSymbolAddress((void**)&w2b, g_w2b);
    cudaGetSymbolAddress((void**)&w3a, g_w3a);
    cudaGetSymbolAddress((void**)&w3b, g_w3b);
    cudaGetSymbolAddress((void**)&sum1, g_sum1);
    cudaGetSymbolAddress((void**)&sq1,  g_sq1);
    cudaGetSymbolAddress((void**)&sum2, g_sum2);
    cudaGetSymbolAddress((void**)&sq2,  g_sq2);
    cudaGetSymbolAddress((void**)&sum3, g_sum3);
    cudaGetSymbolAddress((void**)&sq3,  g_sq3);

    const int SML1 = 2 * 4 * ARRB;    // 81920 B
    const int SMV2 = 2 * 3 * ARR2B;   // 110592 B
    cudaFuncSetAttribute(gemm_l1, cudaFuncAttributeMaxDynamicSharedMemorySize, SML1);
    cudaFuncSetAttribute(gemm_v2, cudaFuncAttributeMaxDynamicSharedMemorySize, SMV2);

    // 0: prep (vectorized, 4 elems/thread)
    prep_all<<<(unsigned)(((size_t)MM * JJ / 4 + 255) / 256), 256>>>(x, W1, W2, W3);

    // 1: layer-1 fused GEMM (+stats)
    gemm_l1<<<dim3(HH / 128, MM / 128), 256, SML1>>>(x0, x1, w1a, w1b, h, sum1, sq1, HH, JJ);
    // 2: lif 1
    lif_scan<__half><<<(BB * HH + 255) / 256, 256>>>(h, sum1, sq1, gamma1, bias1, beta1, U01, s16, BB, TT, HH);

    // 3: layer-2 GEMM (+stats)  <-- ncu captures this
    gemm_v2<<<dim3(HH / 128, MM / 128), 256, SMV2>>>(s16, w2a, w2b, h, sum2, sq2, HH, HH);
    // 4: lif 2
    lif_scan<__half><<<(BB * HH + 255) / 256, 256>>>(h, sum2, sq2, gamma2, bias2, beta2, U02, s16, BB, TT, HH);

    // 5: layer-3 GEMM (+stats)
    gemm_v2<<<dim3(JJ / 128, MM / 128), 256, SMV2>>>(s16, w3a, w3b, h, sum3, sq3, JJ, HH);
    // 6: lif 3
    lif_scan<float><<<(BB * JJ + 255) / 256, 256>>>(h, sum3, sq3, gamma3, bias3, beta3, U03, out, BB, TT, JJ);
}